// round 1
// baseline (speedup 1.0000x reference)
#include <cuda_runtime.h>
#include <math.h>

#define NQ 8
#define NL 3
#define NA 2
#define NB 16
#define NTHREADS 256
#define DIMF 16384   // 2^(8 + 2*3)

// smem layout: state (DIMF float2) | phi (256 float) | red (8*NTHREADS float)
#define SMEM_BYTES (DIMF*8 + 256*4 + 8*NTHREADS*4)

__device__ __forceinline__ float2 cmul(float2 a, float2 b){
    return make_float2(fmaf(a.x, b.x, -a.y*b.y), fmaf(a.x, b.y, a.y*b.x));
}
__device__ __forceinline__ float2 cadd(float2 a, float2 b){
    return make_float2(a.x + b.x, a.y + b.y);
}

// generic single-qubit gate on qubit q (dim = current state size)
__device__ void apply1(float2* st, int dim, int q,
                       float2 u00, float2 u01, float2 u10, float2 u11){
    int half = dim >> 1;
    int mask = (1 << q) - 1;
    for (int k = threadIdx.x; k < half; k += NTHREADS){
        int i0 = ((k & ~mask) << 1) | (k & mask);
        int i1 = i0 | (1 << q);
        float2 a = st[i0], b = st[i1];
        st[i0] = cadd(cmul(u00, a), cmul(u01, b));
        st[i1] = cadd(cmul(u10, a), cmul(u11, b));
    }
    __syncthreads();
}

// fused RXX(txx)*RYY(tyy)*RZZ(tzz) on a qubit pair (symmetric in the two wires)
__device__ void apply_pair(float2* st, int dim, int qa, int qb,
                           float txx, float tyy, float tzz){
    float ca, sa, cb, sb, cg, sg;
    sincosf(0.5f * txx, &sa, &ca);
    sincosf(0.5f * tyy, &sb, &cb);
    sincosf(0.5f * tzz, &sg, &cg);
    // Ryy*Rxx on {00,11}: [[A, i*Bi],[i*Bi, A]]   A = ca*cb + sa*sb, Bi = ca*sb - cb*sa
    //           on {01,10}: [[C, i*Di],[i*Di, C]] C = ca*cb - sa*sb, Di = -(sa*cb + ca*sb)
    // Rzz scales {00,11} rows by e^{-i tzz/2}, {01,10} rows by e^{+i tzz/2}
    float A  = ca*cb + sa*sb;
    float Bi = ca*sb - cb*sa;
    float C  = ca*cb - sa*sb;
    float Di = -(sa*cb + ca*sb);
    float2 p  = make_float2(cg, -sg);
    float2 qf = make_float2(cg,  sg);
    float2 pA = make_float2(p.x*A,  p.y*A);
    float2 pB = cmul(p,  make_float2(0.f, Bi));
    float2 qC = make_float2(qf.x*C, qf.y*C);
    float2 qD = cmul(qf, make_float2(0.f, Di));

    int qlo = qa < qb ? qa : qb;
    int qhi = qa ^ qb ^ qlo;
    int ml = (1 << qlo) - 1;
    int mh = (1 << qhi) - 1;
    int quarter = dim >> 2;
    for (int k = threadIdx.x; k < quarter; k += NTHREADS){
        int t    = ((k & ~ml) << 1) | (k & ml);
        int base = ((t & ~mh) << 1) | (t & mh);
        int iA = base | (1 << qlo);           // one bit set
        int iB = base | (1 << qhi);           // other bit set
        int iC = base | (1 << qlo) | (1 << qhi);  // both
        float2 s00 = st[base], s01 = st[iA], s10 = st[iB], s11 = st[iC];
        st[base] = cadd(cmul(pA, s00), cmul(pB, s11));
        st[iC]   = cadd(cmul(pB, s00), cmul(pA, s11));
        st[iA]   = cadd(cmul(qC, s01), cmul(qD, s10));
        st[iB]   = cadd(cmul(qD, s01), cmul(qC, s10));
    }
    __syncthreads();
}

// CCRX(pi/4) on q2, controlled on bits rec==1 and q1==1
__device__ void ccrx(float2* st, int dim, int rec, int q1, int q2){
    const float c8 = 0.9238795325112867f;  // cos(pi/8)
    const float s8 = 0.3826834323650898f;  // sin(pi/8)
    int mask = (1 << q2) - 1;
    int half = dim >> 1;
    int cbits = (1 << rec) | (1 << q1);
    for (int k = threadIdx.x; k < half; k += NTHREADS){
        int i0 = ((k & ~mask) << 1) | (k & mask);
        if ((i0 & cbits) == cbits){
            int i1 = i0 | (1 << q2);
            float2 a = st[i0], b = st[i1];
            // new0 = c*a + (-i s)*b ; new1 = (-i s)*a + c*b
            st[i0] = make_float2(fmaf(c8, a.x,  s8*b.y), fmaf(c8, a.y, -s8*b.x));
            st[i1] = make_float2(fmaf(s8, a.y,  c8*b.x), fmaf(-s8, a.x, c8*b.y));
        }
    }
    __syncthreads();
}

__global__ void __launch_bounds__(NTHREADS, 1)
qpie_kernel(const float* __restrict__ x,
            const float* __restrict__ w,
            const float* __restrict__ pw,
            float* __restrict__ out)
{
    extern __shared__ float smem_raw[];
    float2* st  = (float2*)smem_raw;
    float*  phi = smem_raw + 2*DIMF;
    float*  red = phi + 256;

    int b   = blockIdx.x;
    int tid = threadIdx.x;
    const float* xb = x + b*NQ;

    // initial state: |0>^T with H on the 8 data qubits -> uniform 2^-4 over 256 states
    for (int s = tid; s < 256; s += NTHREADS) st[s] = make_float2(0.0625f, 0.f);
    __syncthreads();

    int dim = 256;
    for (int layer = 0; layer < NL; ++layer){
        const float* wl = w + layer*48;

        // data rotations (Ry even layer, Rx odd layer) with angle x[q]
        for (int q = 0; q < NQ; ++q){
            float c, s;
            sincosf(0.5f * xb[q], &s, &c);
            if (layer & 1){ // Rx
                apply1(st, dim, q, make_float2(c,0), make_float2(0,-s),
                                    make_float2(0,-s), make_float2(c,0));
            } else {        // Ry
                apply1(st, dim, q, make_float2(c,0), make_float2(-s,0),
                                    make_float2(s,0), make_float2(c,0));
            }
        }

        // ancilla H + CRZ phases + (H if odd layer) + SWAP to record
        // == append a new qubit with per-data-pattern factors
        for (int i = 0; i < NA; ++i){
            const float* pwa = pw + (layer*NA + i)*NQ;
            for (int s = tid; s < 256; s += NTHREADS){
                float acc = 0.f;
                #pragma unroll
                for (int j = 0; j < NQ; ++j)
                    if ((s >> j) & 1) acc += pwa[j];
                phi[s] = 0.5f * acc;
            }
            __syncthreads();
            if ((layer & 1) == 0){
                const float R = 0.7071067811865476f;
                for (int k = tid; k < dim; k += NTHREADS){
                    float ph = phi[k & 255];
                    float sp, cp; sincosf(ph, &sp, &cp);
                    float2 a = st[k];
                    st[k]       = cmul(a, make_float2(cp*R, -sp*R)); // e^{-i phi}/sqrt2
                    st[k + dim] = cmul(a, make_float2(cp*R,  sp*R)); // e^{+i phi}/sqrt2
                }
            } else {
                for (int k = tid; k < dim; k += NTHREADS){
                    float ph = phi[k & 255];
                    float sp, cp; sincosf(ph, &sp, &cp);
                    float2 a = st[k];
                    st[k]       = make_float2(a.x*cp, a.y*cp);   // cos(phi)
                    st[k + dim] = make_float2(a.y*sp, -a.x*sp);  // -i sin(phi)
                }
            }
            __syncthreads();
            dim <<= 1;
        }

        // entangling pairs + CCRX with this layer's record qubits
        int rec0 = 8 + 2*layer;
        for (int i = 0; i < 4; ++i){
            int q1 = 2*i, q2 = 2*i + 1;
            apply_pair(st, dim, q1, q2, wl[3*i], wl[3*i+1], wl[3*i+2]);
            if (i < NA) ccrx(st, dim, rec0 + i, q1, q2);
        }
        // offset pairs
        for (int i = 0; i < 3; ++i){
            int q1 = 2*i + 1, q2 = 2*i + 2;
            int idx = 4 + i;
            apply_pair(st, dim, q1, q2, wl[3*idx], wl[3*idx+1], wl[3*idx+2]);
        }

        // final per-qubit RX,RY,RZ fused into one 2x2: U = Rz*Ry*Rx
        const float* vw = wl + 24;
        for (int q = 0; q < NQ; ++q){
            float s1, c1, s2, c2, sz, cz;
            sincosf(0.5f * vw[3*q+0], &s1, &c1);
            sincosf(0.5f * vw[3*q+1], &s2, &c2);
            sincosf(0.5f * vw[3*q+2], &sz, &cz);
            float2 m00 = make_float2( c1*c2,  s1*s2);
            float2 m01 = make_float2(-c1*s2, -c2*s1);
            float2 m10 = make_float2( c1*s2, -c2*s1);
            float2 m11 = make_float2( c1*c2, -s1*s2);
            float2 e0 = make_float2(cz, -sz);
            float2 e1 = make_float2(cz,  sz);
            apply1(st, dim, q, cmul(e0, m00), cmul(e0, m01),
                                cmul(e1, m10), cmul(e1, m11));
        }
    }

    // expectation values <Z_q> for the 8 data qubits
    float ev[NQ];
    #pragma unroll
    for (int q = 0; q < NQ; ++q) ev[q] = 0.f;
    for (int k = tid; k < dim; k += NTHREADS){
        float2 a = st[k];
        float p = fmaf(a.x, a.x, a.y*a.y);
        #pragma unroll
        for (int q = 0; q < NQ; ++q)
            ev[q] += ((k >> q) & 1) ? -p : p;
    }
    #pragma unroll
    for (int q = 0; q < NQ; ++q) red[q*NTHREADS + tid] = ev[q];
    __syncthreads();
    // tree reduce each of the 8 sums
    for (int stride = NTHREADS/2; stride > 0; stride >>= 1){
        if (tid < stride){
            #pragma unroll
            for (int q = 0; q < NQ; ++q)
                red[q*NTHREADS + tid] += red[q*NTHREADS + tid + stride];
        }
        __syncthreads();
    }
    if (tid < NQ) out[b*NQ + tid] = red[tid*NTHREADS];
}

extern "C" void kernel_launch(void* const* d_in, const int* in_sizes, int n_in,
                              void* d_out, int out_size){
    const float* x  = (const float*)d_in[0];   // (16, 8)
    const float* w  = (const float*)d_in[1];   // (3, 48)
    const float* pw = (const float*)d_in[2];   // (3, 2, 8)
    float* out = (float*)d_out;                // (16, 8) float32

    cudaFuncSetAttribute(qpie_kernel,
                         cudaFuncAttributeMaxDynamicSharedMemorySize, SMEM_BYTES);
    qpie_kernel<<<NB, NTHREADS, SMEM_BYTES>>>(x, w, pw, out);
}

// round 2
// speedup vs baseline: 5.9150x; 5.9150x over previous
#include <cuda_runtime.h>
#include <math.h>

#define NB   16          // batch
#define NBR  64          // branches (2^6 record bits)
#define WPC  8           // warps per CTA
#define CTA_THREADS 256
#define NCTA ((NB*NBR)/WPC)   // 128

__device__ float g_part[NB*NBR*8];

__device__ __forceinline__ float2 cmul(float2 a, float2 b){
    return make_float2(fmaf(a.x, b.x, -a.y*b.y), fmaf(a.x, b.y, a.y*b.x));
}
__device__ __forceinline__ float2 cadd(float2 a, float2 b){
    return make_float2(a.x + b.x, a.y + b.y);
}
__device__ __forceinline__ float2 shflx(float2 v, int m){
    float2 r;
    r.x = __shfl_xor_sync(0xffffffffu, v.x, m);
    r.y = __shfl_xor_sync(0xffffffffu, v.y, m);
    return r;
}

// single-qubit gate on local register bit q (0..2)
__device__ __forceinline__ void sq_local(float2* a, int q,
        float2 u00, float2 u01, float2 u10, float2 u11){
    int m = 1 << q;
    #pragma unroll
    for (int i = 0; i < 8; i++){
        if (!(i & m)){
            int j = i | m;
            float2 x = a[i], y = a[j];
            a[i] = cadd(cmul(u00, x), cmul(u01, y));
            a[j] = cadd(cmul(u10, x), cmul(u11, y));
        }
    }
}

// single-qubit gate on lane bit lb (qubit 3+lb)
__device__ __forceinline__ void sq_lane(float2* a, int lane, int lb,
        float2 u00, float2 u01, float2 u10, float2 u11){
    int m = 1 << lb;
    bool hi = (lane >> lb) & 1;
    float2 cs = hi ? u11 : u00;   // self coefficient
    float2 cx = hi ? u10 : u01;   // cross coefficient
    #pragma unroll
    for (int i = 0; i < 8; i++){
        float2 p = shflx(a[i], m);
        a[i] = cadd(cmul(cs, a[i]), cmul(cx, p));
    }
}

// fused RXX*RYY*RZZ coefficients (verified in round 1)
__device__ __forceinline__ void pair_coef(float txx, float tyy, float tzz,
        float2& pA, float2& pB, float2& qC, float2& qD){
    float ca, sa, cb, sb, cg, sg;
    __sincosf(0.5f*txx, &sa, &ca);
    __sincosf(0.5f*tyy, &sb, &cb);
    __sincosf(0.5f*tzz, &sg, &cg);
    float A  = ca*cb + sa*sb;
    float Bi = ca*sb - cb*sa;
    float C  = ca*cb - sa*sb;
    float Di = -(sa*cb + ca*sb);
    float2 p  = make_float2(cg, -sg);
    float2 qf = make_float2(cg,  sg);
    pA = make_float2(p.x*A,  p.y*A);
    pB = cmul(p,  make_float2(0.f, Bi));
    qC = make_float2(qf.x*C, qf.y*C);
    qD = cmul(qf, make_float2(0.f, Di));
}

// pair gate, both qubits local bits A < B
__device__ __forceinline__ void pair_LL(float2* a, int A, int B,
        float2 pA, float2 pB, float2 qC, float2 qD){
    int M = (1<<A) | (1<<B);
    #pragma unroll
    for (int i = 0; i < 8; i++){
        if (!((i >> B) & 1)){
            int j = i ^ M;
            bool eq = !((i >> A) & 1);   // since bit B of i is 0
            float2 X = eq ? pA : qC;
            float2 Y = eq ? pB : qD;
            float2 ai = a[i], aj = a[j];
            a[i] = cadd(cmul(X, ai), cmul(Y, aj));
            a[j] = cadd(cmul(Y, ai), cmul(X, aj));
        }
    }
}

// pair gate, both qubits lane bits LA, LB
__device__ __forceinline__ void pair_NN(float2* a, int lane, int LA, int LB,
        float2 pA, float2 pB, float2 qC, float2 qD){
    int M = (1<<LA) | (1<<LB);
    bool eq = ((((lane >> LA) ^ (lane >> LB)) & 1) == 0);
    float2 X = eq ? pA : qC;
    float2 Y = eq ? pB : qD;
    #pragma unroll
    for (int i = 0; i < 8; i++){
        float2 p = shflx(a[i], M);
        a[i] = cadd(cmul(X, a[i]), cmul(Y, p));
    }
}

// pair gate, local bit A + lane bit LB (qubits 2 and 3 -> A=2, LB=0)
__device__ __forceinline__ void pair_ML(float2* a, int lane, int A, int LB,
        float2 pA, float2 pB, float2 qC, float2 qD){
    int lm = 1 << LB;
    int b4 = (lane >> LB) & 1;
    float2 Xi = b4 ? qC : pA, Yi = b4 ? qD : pB;   // a[i]: local bit A = 0
    float2 Xj = b4 ? pA : qC, Yj = b4 ? pB : qD;   // a[j]: local bit A = 1
    #pragma unroll
    for (int i = 0; i < 8; i++){
        if (!((i >> A) & 1)){
            int j = i | (1 << A);
            float2 pj = shflx(a[j], lm);
            float2 pi = shflx(a[i], lm);
            a[i] = cadd(cmul(Xi, a[i]), cmul(Yi, pj));
            a[j] = cadd(cmul(Xj, a[j]), cmul(Yj, pi));
        }
    }
}

__global__ void __launch_bounds__(CTA_THREADS, 1)
qpie_main(const float* __restrict__ x,
          const float* __restrict__ w,
          const float* __restrict__ pw)
{
    const float c8 = 0.9238795325112867f;   // cos(pi/8)
    const float s8 = 0.3826834323650898f;   // sin(pi/8)
    const float RH = 0.7071067811865476f;

    int lane = threadIdx.x & 31;
    int gw   = blockIdx.x * WPC + (threadIdx.x >> 5);
    int b    = gw >> 6;
    int br   = gw & 63;          // record bits r8..r13
    const float* xb = x + b*8;

    // state: 8 local amps (bits 0-2 = qubits 0-2), lane bits 0-4 = qubits 3-7
    float2 a[8];
    #pragma unroll
    for (int i = 0; i < 8; i++) a[i] = make_float2(0.0625f, 0.f);

    for (int layer = 0; layer < 3; ++layer){
        const float* wl = w + layer*48;
        int odd = layer & 1;

        // ---- data rotations (Ry even / Rx odd), angle x[q] ----
        #pragma unroll
        for (int q = 0; q < 8; q++){
            float s, c; __sincosf(0.5f*xb[q], &s, &c);
            float2 u00, u01, u10, u11;
            if (odd){ u00 = make_float2(c,0); u01 = make_float2(0,-s);
                      u10 = u01;              u11 = u00; }
            else    { u00 = make_float2(c,0); u01 = make_float2(-s,0);
                      u10 = make_float2(s,0); u11 = u00; }
            if (q < 3) sq_local(a, q, u00, u01, u10, u11);
            else       sq_lane (a, lane, q-3, u00, u01, u10, u11);
        }

        // ---- record-qubit creation, branch bit fixed -> diagonal factor ----
        #pragma unroll
        for (int i2 = 0; i2 < 2; i2++){
            int v = (br >> (2*layer + i2)) & 1;
            const float* pwa = pw + (layer*2 + i2)*8;
            float lanesum = 0.f;
            #pragma unroll
            for (int j = 0; j < 5; j++)
                if ((lane >> j) & 1) lanesum += pwa[3+j];
            #pragma unroll
            for (int i = 0; i < 8; i++){
                float ph = lanesum;
                #pragma unroll
                for (int j = 0; j < 3; j++)
                    if ((i >> j) & 1) ph += pwa[j];
                ph *= 0.5f;
                float sp, cp; __sincosf(ph, &sp, &cp);
                float2 f;
                if (!odd) f = v ? make_float2(cp*RH,  sp*RH)
                                : make_float2(cp*RH, -sp*RH);
                else      f = v ? make_float2(0.f, -sp)
                                : make_float2(cp, 0.f);
                a[i] = cmul(a[i], f);
            }
        }

        // ---- entangling pairs + CCRX ----
        float2 pA, pB, qC, qD;
        // pair (0,1) local-local
        pair_coef(wl[0], wl[1], wl[2], pA, pB, qC, qD);
        pair_LL(a, 0, 1, pA, pB, qC, qD);
        // CCRX rec(2*layer), control q1=0 (local bit0), target q2=1 (local bit1)
        if ((br >> (2*layer)) & 1){
            #pragma unroll
            for (int i = 0; i < 8; i++){
                if ((i & 1) && !(i & 2)){
                    int j = i | 2;
                    float2 ai = a[i], aj = a[j];
                    a[i] = make_float2(fmaf(c8, ai.x,  s8*aj.y), fmaf(c8, ai.y, -s8*aj.x));
                    a[j] = make_float2(fmaf(c8, aj.x,  s8*ai.y), fmaf(c8, aj.y, -s8*ai.x));
                }
            }
        }
        // pair (2,3): local bit2 + lane bit0
        pair_coef(wl[3], wl[4], wl[5], pA, pB, qC, qD);
        pair_ML(a, lane, 2, 0, pA, pB, qC, qD);
        // CCRX rec(2*layer+1), control q1=2 (local bit2), target q2=3 (lane bit0)
        if ((br >> (2*layer + 1)) & 1){   // warp-uniform predicate
            #pragma unroll
            for (int i = 4; i < 8; i++){  // local bit2 = 1
                float2 p = shflx(a[i], 1);
                a[i] = make_float2(fmaf(c8, a[i].x,  s8*p.y), fmaf(c8, a[i].y, -s8*p.x));
            }
        }
        // pair (4,5): lane bits 1,2
        pair_coef(wl[6], wl[7], wl[8], pA, pB, qC, qD);
        pair_NN(a, lane, 1, 2, pA, pB, qC, qD);
        // pair (6,7): lane bits 3,4
        pair_coef(wl[9], wl[10], wl[11], pA, pB, qC, qD);
        pair_NN(a, lane, 3, 4, pA, pB, qC, qD);
        // offset pair (1,2) local-local
        pair_coef(wl[12], wl[13], wl[14], pA, pB, qC, qD);
        pair_LL(a, 1, 2, pA, pB, qC, qD);
        // offset pair (3,4): lane bits 0,1
        pair_coef(wl[15], wl[16], wl[17], pA, pB, qC, qD);
        pair_NN(a, lane, 0, 1, pA, pB, qC, qD);
        // offset pair (5,6): lane bits 2,3
        pair_coef(wl[18], wl[19], wl[20], pA, pB, qC, qD);
        pair_NN(a, lane, 2, 3, pA, pB, qC, qD);

        // ---- final per-qubit RZ*RY*RX fused ----
        const float* vw = wl + 24;
        #pragma unroll
        for (int q = 0; q < 8; q++){
            float s1, c1, s2, c2, sz, cz;
            __sincosf(0.5f*vw[3*q+0], &s1, &c1);
            __sincosf(0.5f*vw[3*q+1], &s2, &c2);
            __sincosf(0.5f*vw[3*q+2], &sz, &cz);
            float2 m00 = make_float2( c1*c2,  s1*s2);
            float2 m01 = make_float2(-c1*s2, -c2*s1);
            float2 m10 = make_float2( c1*s2, -c2*s1);
            float2 m11 = make_float2( c1*c2, -s1*s2);
            float2 e0 = make_float2(cz, -sz);
            float2 e1 = make_float2(cz,  sz);
            float2 u00 = cmul(e0, m00), u01 = cmul(e0, m01);
            float2 u10 = cmul(e1, m10), u11 = cmul(e1, m11);
            if (q < 3) sq_local(a, q, u00, u01, u10, u11);
            else       sq_lane (a, lane, q-3, u00, u01, u10, u11);
        }
    }

    // ---- measurement: <Z_q> partials for this branch ----
    float e[8];
    float tot = 0.f;
    #pragma unroll
    for (int q = 0; q < 3; q++) e[q] = 0.f;
    #pragma unroll
    for (int i = 0; i < 8; i++){
        float p = fmaf(a[i].x, a[i].x, a[i].y*a[i].y);
        tot += p;
        #pragma unroll
        for (int q = 0; q < 3; q++)
            e[q] += ((i >> q) & 1) ? -p : p;
    }
    #pragma unroll
    for (int q = 0; q < 5; q++)
        e[3+q] = ((lane >> q) & 1) ? -tot : tot;

    #pragma unroll
    for (int q = 0; q < 8; q++){
        #pragma unroll
        for (int s = 16; s; s >>= 1)
            e[q] += __shfl_xor_sync(0xffffffffu, e[q], s);
    }
    if (lane == 0){
        #pragma unroll
        for (int q = 0; q < 8; q++) g_part[gw*8 + q] = e[q];
    }
}

__global__ void qpie_reduce(float* __restrict__ out){
    int t = threadIdx.x;        // 128 = 16 batches * 8 qubits
    int b = t >> 3, q = t & 7;
    float s = 0.f;
    #pragma unroll
    for (int br = 0; br < NBR; br++)
        s += g_part[((b << 6) + br)*8 + q];
    out[t] = s;
}

extern "C" void kernel_launch(void* const* d_in, const int* in_sizes, int n_in,
                              void* d_out, int out_size){
    const float* x  = (const float*)d_in[0];   // (16, 8)
    const float* w  = (const float*)d_in[1];   // (3, 48)
    const float* pw = (const float*)d_in[2];   // (3, 2, 8)
    float* out = (float*)d_out;                // (16, 8)

    qpie_main<<<NCTA, CTA_THREADS>>>(x, w, pw);
    qpie_reduce<<<1, 128>>>(out);
}

// round 3
// speedup vs baseline: 7.9383x; 1.3421x over previous
#include <cuda_runtime.h>

#define NB   16
#define WPC  8
#define CTA_THREADS 256
#define NCTA 128          // 16 batches * 64 branches / 8 warps per CTA

__device__ float g_part[NCTA*8];
__device__ unsigned int g_ticket;   // zero-init; reset to 0 by last CTA each launch

__device__ __forceinline__ float2 cmul(float2 a, float2 b){
    return make_float2(fmaf(a.x, b.x, -a.y*b.y), fmaf(a.x, b.y, a.y*b.x));
}
__device__ __forceinline__ float2 cadd(float2 a, float2 b){
    return make_float2(a.x + b.x, a.y + b.y);
}
__device__ __forceinline__ float2 shflx(float2 v, int m){
    float2 r;
    r.x = __shfl_xor_sync(0xffffffffu, v.x, m);
    r.y = __shfl_xor_sync(0xffffffffu, v.y, m);
    return r;
}

// ---------------- generic single-qubit gates (used for final rotations) ----------
__device__ __forceinline__ void sq_local(float2* a, int q,
        float2 u00, float2 u01, float2 u10, float2 u11){
    int m = 1 << q;
    #pragma unroll
    for (int i = 0; i < 8; i++){
        if (!(i & m)){
            int j = i | m;
            float2 x = a[i], y = a[j];
            a[i] = cadd(cmul(u00, x), cmul(u01, y));
            a[j] = cadd(cmul(u10, x), cmul(u11, y));
        }
    }
}
__device__ __forceinline__ void sq_lane(float2* a, int lane, int lb,
        float2 u00, float2 u01, float2 u10, float2 u11){
    int m = 1 << lb;
    bool hi = (lane >> lb) & 1;
    float2 cs = hi ? u11 : u00;
    float2 cx = hi ? u10 : u01;
    #pragma unroll
    for (int i = 0; i < 8; i++){
        float2 p = shflx(a[i], m);
        a[i] = cadd(cmul(cs, a[i]), cmul(cx, p));
    }
}

// ---------------- specialized Rx/Ry data rotations -------------------------------
__device__ __forceinline__ void ry_local(float2* a, int q, float c, float s){
    int m = 1 << q;
    #pragma unroll
    for (int i = 0; i < 8; i++){
        if (!(i & m)){
            int j = i | m;
            float2 x = a[i], y = a[j];
            a[i] = make_float2(fmaf(c, x.x, -s*y.x), fmaf(c, x.y, -s*y.y));
            a[j] = make_float2(fmaf(s, x.x,  c*y.x), fmaf(s, x.y,  c*y.y));
        }
    }
}
__device__ __forceinline__ void ry_lane(float2* a, int lane, int lb, float c, float s){
    int m = 1 << lb;
    float cx = ((lane >> lb) & 1) ? s : -s;
    #pragma unroll
    for (int i = 0; i < 8; i++){
        float2 p = shflx(a[i], m);
        a[i] = make_float2(fmaf(c, a[i].x, cx*p.x), fmaf(c, a[i].y, cx*p.y));
    }
}
__device__ __forceinline__ void rx_local(float2* a, int q, float c, float s){
    int m = 1 << q;
    #pragma unroll
    for (int i = 0; i < 8; i++){
        if (!(i & m)){
            int j = i | m;
            float2 x = a[i], y = a[j];
            a[i] = make_float2(fmaf(c, x.x,  s*y.y), fmaf(c, x.y, -s*y.x));
            a[j] = make_float2(fmaf(c, y.x,  s*x.y), fmaf(c, y.y, -s*x.x));
        }
    }
}
__device__ __forceinline__ void rx_lane(float2* a, int lane, int lb, float c, float s){
    int m = 1 << lb;
    #pragma unroll
    for (int i = 0; i < 8; i++){
        float2 p = shflx(a[i], m);
        a[i] = make_float2(fmaf(c, a[i].x, s*p.y), fmaf(c, a[i].y, -s*p.x));
    }
}

// ---------------- pair gates (fused RXX*RYY*RZZ) ---------------------------------
__device__ __forceinline__ void pair_LL(float2* a, int A, int B,
        float2 pA, float2 pB, float2 qC, float2 qD){
    int M = (1<<A) | (1<<B);
    #pragma unroll
    for (int i = 0; i < 8; i++){
        if (!((i >> B) & 1)){
            int j = i ^ M;
            bool eq = !((i >> A) & 1);
            float2 X = eq ? pA : qC;
            float2 Y = eq ? pB : qD;
            float2 ai = a[i], aj = a[j];
            a[i] = cadd(cmul(X, ai), cmul(Y, aj));
            a[j] = cadd(cmul(Y, ai), cmul(X, aj));
        }
    }
}
__device__ __forceinline__ void pair_NN(float2* a, int lane, int LA, int LB,
        float2 pA, float2 pB, float2 qC, float2 qD){
    int M = (1<<LA) | (1<<LB);
    bool eq = ((((lane >> LA) ^ (lane >> LB)) & 1) == 0);
    float2 X = eq ? pA : qC;
    float2 Y = eq ? pB : qD;
    #pragma unroll
    for (int i = 0; i < 8; i++){
        float2 p = shflx(a[i], M);
        a[i] = cadd(cmul(X, a[i]), cmul(Y, p));
    }
}
__device__ __forceinline__ void pair_ML(float2* a, int lane, int A, int LB,
        float2 pA, float2 pB, float2 qC, float2 qD){
    int lm = 1 << LB;
    int b4 = (lane >> LB) & 1;
    float2 Xi = b4 ? qC : pA, Yi = b4 ? qD : pB;
    float2 Xj = b4 ? pA : qC, Yj = b4 ? pB : qD;
    #pragma unroll
    for (int i = 0; i < 8; i++){
        if (!((i >> A) & 1)){
            int j = i | (1 << A);
            float2 pj = shflx(a[j], lm);
            float2 pi = shflx(a[i], lm);
            a[i] = cadd(cmul(Xi, a[i]), cmul(Yi, pj));
            a[j] = cadd(cmul(Xj, a[j]), cmul(Yj, pi));
        }
    }
}

__global__ void __launch_bounds__(CTA_THREADS, 1)
qpie_fused(const float* __restrict__ x,
           const float* __restrict__ w,
           const float* __restrict__ pw,
           float* __restrict__ out)
{
    const float c8 = 0.9238795325112867f;   // cos(pi/8)
    const float s8 = 0.3826834323650898f;   // sin(pi/8)
    const float RH = 0.7071067811865476f;

    __shared__ float2 sXcs[8];          // data-rot (c,s) for this batch
    __shared__ float2 sLane[6*32];      // e^{i*lanesum/2} per record, lane
    __shared__ float2 sLoc[6*8];        // e^{i*locsum/2} per record, local idx
    __shared__ float2 sPair[21*4];      // pA,pB,qC,qD per (layer,pair)
    __shared__ float2 sFin[24*4];       // u00..u11 per (layer,q)
    __shared__ float  sRed[8*8];        // per-warp partials
    __shared__ int    sLast;

    int tid  = threadIdx.x;
    int lane = tid & 31;
    int wid  = tid >> 5;
    int cta  = blockIdx.x;
    int b    = cta >> 3;                // 8 CTAs per batch
    int gw   = cta*WPC + wid;
    int br   = gw & 63;                 // record-bit branch

    // ================= cooperative coefficient-table build =================
    for (int job = tid; job < 293; job += CTA_THREADS){
        if (job < 8){
            float s, c; __sincosf(0.5f*x[b*8 + job], &s, &c);
            sXcs[job] = make_float2(c, s);
        } else if (job < 200){
            int k = job - 8; int r = k >> 5; int ln = k & 31;
            const float* pwa = pw + r*8;
            float sum = 0.f;
            #pragma unroll
            for (int j = 0; j < 5; j++)
                if ((ln >> j) & 1) sum += pwa[3+j];
            float sp, cp; __sincosf(0.5f*sum, &sp, &cp);
            sLane[k] = make_float2(cp, sp);
        } else if (job < 248){
            int k = job - 200; int r = k >> 3; int i = k & 7;
            const float* pwa = pw + r*8;
            float sum = 0.f;
            #pragma unroll
            for (int j = 0; j < 3; j++)
                if ((i >> j) & 1) sum += pwa[j];
            float sp, cp; __sincosf(0.5f*sum, &sp, &cp);
            sLoc[k] = make_float2(cp, sp);
        } else if (job < 269){
            int k = job - 248; int layer = k/7, p = k - layer*7;
            const float* wl = w + layer*48 + 3*p;
            float ca, sa, cb, sb, cg, sg;
            __sincosf(0.5f*wl[0], &sa, &ca);
            __sincosf(0.5f*wl[1], &sb, &cb);
            __sincosf(0.5f*wl[2], &sg, &cg);
            float A  = ca*cb + sa*sb;
            float Bi = ca*sb - cb*sa;
            float C  = ca*cb - sa*sb;
            float Di = -(sa*cb + ca*sb);
            float2 pph = make_float2(cg, -sg);
            float2 qph = make_float2(cg,  sg);
            sPair[k*4+0] = make_float2(pph.x*A, pph.y*A);
            sPair[k*4+1] = cmul(pph, make_float2(0.f, Bi));
            sPair[k*4+2] = make_float2(qph.x*C, qph.y*C);
            sPair[k*4+3] = cmul(qph, make_float2(0.f, Di));
        } else {
            int k = job - 269; int layer = k >> 3, q = k & 7;
            const float* vw = w + layer*48 + 24 + 3*q;
            float s1, c1, s2, c2, sz, cz;
            __sincosf(0.5f*vw[0], &s1, &c1);
            __sincosf(0.5f*vw[1], &s2, &c2);
            __sincosf(0.5f*vw[2], &sz, &cz);
            float2 m00 = make_float2( c1*c2,  s1*s2);
            float2 m01 = make_float2(-c1*s2, -c2*s1);
            float2 m10 = make_float2( c1*s2, -c2*s1);
            float2 m11 = make_float2( c1*c2, -s1*s2);
            float2 e0 = make_float2(cz, -sz);
            float2 e1 = make_float2(cz,  sz);
            sFin[k*4+0] = cmul(e0, m00);
            sFin[k*4+1] = cmul(e0, m01);
            sFin[k*4+2] = cmul(e1, m10);
            sFin[k*4+3] = cmul(e1, m11);
        }
    }
    __syncthreads();

    // ================= branch simulation (register-resident, zero MUFU) ====
    float2 a[8];
    #pragma unroll
    for (int i = 0; i < 8; i++) a[i] = make_float2(0.0625f, 0.f);

    #pragma unroll
    for (int layer = 0; layer < 3; ++layer){
        int odd = layer & 1;

        // data rotations (Ry even / Rx odd)
        #pragma unroll
        for (int q = 0; q < 8; q++){
            float2 cs = sXcs[q];
            if (!odd){
                if (q < 3) ry_local(a, q, cs.x, cs.y);
                else       ry_lane (a, lane, q-3, cs.x, cs.y);
            } else {
                if (q < 3) rx_local(a, q, cs.x, cs.y);
                else       rx_lane (a, lane, q-3, cs.x, cs.y);
            }
        }

        // record-qubit creation -> diagonal factor per branch bit
        #pragma unroll
        for (int i2 = 0; i2 < 2; i2++){
            int r = layer*2 + i2;
            int v = (br >> r) & 1;
            float2 eL = sLane[r*32 + lane];
            #pragma unroll
            for (int i = 0; i < 8; i++){
                float2 e = cmul(eL, sLoc[r*8 + i]);   // (cos ph, sin ph)
                if (!odd){
                    float sy = v ? e.y : -e.y;
                    a[i] = cmul(a[i], make_float2(e.x*RH, sy*RH));
                } else {
                    if (v) a[i] = make_float2(a[i].y*e.y, -a[i].x*e.y);   // (0,-sin)
                    else   a[i] = make_float2(a[i].x*e.x,  a[i].y*e.x);   // (cos,0)
                }
            }
        }

        // entangling pairs + CCRX
        const float2* P = sPair + layer*7*4;
        pair_LL(a, 0, 1, P[0], P[1], P[2], P[3]);
        if ((br >> (2*layer)) & 1){
            #pragma unroll
            for (int i = 0; i < 8; i++){
                if ((i & 1) && !(i & 2)){
                    int j = i | 2;
                    float2 ai = a[i], aj = a[j];
                    a[i] = make_float2(fmaf(c8, ai.x,  s8*aj.y), fmaf(c8, ai.y, -s8*aj.x));
                    a[j] = make_float2(fmaf(c8, aj.x,  s8*ai.y), fmaf(c8, aj.y, -s8*ai.x));
                }
            }
        }
        pair_ML(a, lane, 2, 0, P[4], P[5], P[6], P[7]);
        if ((br >> (2*layer + 1)) & 1){
            #pragma unroll
            for (int i = 4; i < 8; i++){
                float2 p = shflx(a[i], 1);
                a[i] = make_float2(fmaf(c8, a[i].x,  s8*p.y), fmaf(c8, a[i].y, -s8*p.x));
            }
        }
        pair_NN(a, lane, 1, 2, P[8],  P[9],  P[10], P[11]);
        pair_NN(a, lane, 3, 4, P[12], P[13], P[14], P[15]);
        pair_LL(a, 1, 2,       P[16], P[17], P[18], P[19]);
        pair_NN(a, lane, 0, 1, P[20], P[21], P[22], P[23]);
        pair_NN(a, lane, 2, 3, P[24], P[25], P[26], P[27]);

        // final fused RZ*RY*RX per qubit
        const float2* F = sFin + layer*8*4;
        #pragma unroll
        for (int q = 0; q < 8; q++){
            float2 u00 = F[q*4+0], u01 = F[q*4+1], u10 = F[q*4+2], u11 = F[q*4+3];
            if (q < 3) sq_local(a, q, u00, u01, u10, u11);
            else       sq_lane (a, lane, q-3, u00, u01, u10, u11);
        }
    }

    // ================= measurement & fused reduction =======================
    float e[8];
    float tot = 0.f;
    #pragma unroll
    for (int q = 0; q < 3; q++) e[q] = 0.f;
    #pragma unroll
    for (int i = 0; i < 8; i++){
        float p = fmaf(a[i].x, a[i].x, a[i].y*a[i].y);
        tot += p;
        #pragma unroll
        for (int q = 0; q < 3; q++)
            e[q] += ((i >> q) & 1) ? -p : p;
    }
    #pragma unroll
    for (int q = 0; q < 5; q++)
        e[3+q] = ((lane >> q) & 1) ? -tot : tot;

    #pragma unroll
    for (int q = 0; q < 8; q++){
        #pragma unroll
        for (int s = 16; s; s >>= 1)
            e[q] += __shfl_xor_sync(0xffffffffu, e[q], s);
    }
    if (lane == 0){
        #pragma unroll
        for (int q = 0; q < 8; q++) sRed[wid*8 + q] = e[q];
    }
    __syncthreads();

    if (tid < 8){
        float s = 0.f;
        #pragma unroll
        for (int wq = 0; wq < 8; wq++) s += sRed[wq*8 + tid];
        g_part[cta*8 + tid] = s;
        __threadfence();
    }
    __syncthreads();

    if (tid == 0){
        __threadfence();
        unsigned int t = atomicAdd(&g_ticket, 1u);
        sLast = (t == NCTA - 1) ? 1 : 0;
    }
    __syncthreads();

    if (sLast){
        __threadfence();                  // acquire: see all CTAs' g_part
        if (tid < 128){
            int bb = tid >> 3, q = tid & 7;
            float s = 0.f;
            #pragma unroll
            for (int k = 0; k < 8; k++)
                s += g_part[(bb*8 + k)*8 + q];
            out[tid] = s;
        }
        __syncthreads();
        if (tid == 0) g_ticket = 0;       // reset for next graph replay
    }
}

extern "C" void kernel_launch(void* const* d_in, const int* in_sizes, int n_in,
                              void* d_out, int out_size){
    const float* x  = (const float*)d_in[0];   // (16, 8)
    const float* w  = (const float*)d_in[1];   // (3, 48)
    const float* pw = (const float*)d_in[2];   // (3, 2, 8)
    float* out = (float*)d_out;                // (16, 8)

    qpie_fused<<<NCTA, CTA_THREADS>>>(x, w, pw, out);
}

// round 5
// speedup vs baseline: 9.2326x; 1.1630x over previous
#include <cuda_runtime.h>

#define NB   16
#define WPC  8
#define CTA_THREADS 256
#define NCTA 128          // 16 batches * 64 branches / 8 warps per CTA

__device__ float g_part[NCTA*8];
__device__ unsigned int g_ticket;   // zero-init; reset by last CTA each launch

__device__ __forceinline__ float2 cmul(float2 a, float2 b){
    return make_float2(fmaf(a.x, b.x, -a.y*b.y), fmaf(a.x, b.y, a.y*b.x));
}
__device__ __forceinline__ float2 cadd(float2 a, float2 b){
    return make_float2(a.x + b.x, a.y + b.y);
}
__device__ __forceinline__ float2 shflx(float2 v, int m){
    float2 r;
    r.x = __shfl_xor_sync(0xffffffffu, v.x, m);
    r.y = __shfl_xor_sync(0xffffffffu, v.y, m);
    return r;
}

// ---------------- generic single-qubit gates -------------------------------------
__device__ __forceinline__ void sq_local(float2* a, int q,
        float2 u00, float2 u01, float2 u10, float2 u11){
    int m = 1 << q;
    #pragma unroll
    for (int i = 0; i < 8; i++){
        if (!(i & m)){
            int j = i | m;
            float2 x = a[i], y = a[j];
            a[i] = cadd(cmul(u00, x), cmul(u01, y));
            a[j] = cadd(cmul(u10, x), cmul(u11, y));
        }
    }
}
__device__ __forceinline__ void sq_lane(float2* a, int lane, int lb,
        float2 u00, float2 u01, float2 u10, float2 u11){
    int m = 1 << lb;
    bool hi = (lane >> lb) & 1;
    float2 cs = hi ? u11 : u00;
    float2 cx = hi ? u10 : u01;
    #pragma unroll
    for (int i = 0; i < 8; i++){
        float2 p = shflx(a[i], m);
        a[i] = cadd(cmul(cs, a[i]), cmul(cx, p));
    }
}

// ---------------- pair gates (fused RXX*RYY*RZZ) ---------------------------------
__device__ __forceinline__ void pair_LL(float2* a, int A, int B,
        float2 pA, float2 pB, float2 qC, float2 qD){
    int M = (1<<A) | (1<<B);
    #pragma unroll
    for (int i = 0; i < 8; i++){
        if (!((i >> B) & 1)){
            int j = i ^ M;
            bool eq = !((i >> A) & 1);
            float2 X = eq ? pA : qC;
            float2 Y = eq ? pB : qD;
            float2 ai = a[i], aj = a[j];
            a[i] = cadd(cmul(X, ai), cmul(Y, aj));
            a[j] = cadd(cmul(Y, ai), cmul(X, aj));
        }
    }
}
__device__ __forceinline__ void pair_NN(float2* a, int lane, int LA, int LB,
        float2 pA, float2 pB, float2 qC, float2 qD){
    int M = (1<<LA) | (1<<LB);
    bool eq = ((((lane >> LA) ^ (lane >> LB)) & 1) == 0);
    float2 X = eq ? pA : qC;
    float2 Y = eq ? pB : qD;
    #pragma unroll
    for (int i = 0; i < 8; i++){
        float2 p = shflx(a[i], M);
        a[i] = cadd(cmul(X, a[i]), cmul(Y, p));
    }
}
__device__ __forceinline__ void pair_ML(float2* a, int lane, int A, int LB,
        float2 pA, float2 pB, float2 qC, float2 qD){
    int lm = 1 << LB;
    int b4 = (lane >> LB) & 1;
    float2 Xi = b4 ? qC : pA, Yi = b4 ? qD : pB;
    float2 Xj = b4 ? pA : qC, Yj = b4 ? pB : qD;
    #pragma unroll
    for (int i = 0; i < 8; i++){
        if (!((i >> A) & 1)){
            int j = i | (1 << A);
            float2 pj = shflx(a[j], lm);
            float2 pi = shflx(a[i], lm);
            a[i] = cadd(cmul(Xi, a[i]), cmul(Yi, pj));
            a[j] = cadd(cmul(Xj, a[j]), cmul(Yj, pi));
        }
    }
}

// final rotation matrix U = Rz(t2)*Ry(t1)*Rx(t0) (verified rounds 1-3)
__device__ __forceinline__ void ufinal(const float* vw,
        float2& u00, float2& u01, float2& u10, float2& u11){
    float s1, c1, s2, c2, sz, cz;
    __sincosf(0.5f*vw[0], &s1, &c1);
    __sincosf(0.5f*vw[1], &s2, &c2);
    __sincosf(0.5f*vw[2], &sz, &cz);
    float2 m00 = make_float2( c1*c2,  s1*s2);
    float2 m01 = make_float2(-c1*s2, -c2*s1);
    float2 m10 = make_float2( c1*s2, -c2*s1);
    float2 m11 = make_float2( c1*c2, -s1*s2);
    float2 e0 = make_float2(cz, -sz);
    float2 e1 = make_float2(cz,  sz);
    u00 = cmul(e0, m00); u01 = cmul(e0, m01);
    u10 = cmul(e1, m10); u11 = cmul(e1, m11);
}

__global__ void __launch_bounds__(CTA_THREADS, 1)
qpie_fused(const float* __restrict__ x,
           const float* __restrict__ w,
           const float* __restrict__ pw,
           float* __restrict__ out)
{
    const float c8 = 0.9238795325112867f;   // cos(pi/8)
    const float s8 = 0.3826834323650898f;   // sin(pi/8)

    __shared__ float2 sT[2*8];        // e^{i pw0r[q]/2} for layer-0 records r=0,1
    __shared__ float2 sXcs[8];        // (cos, sin) of x_q/2
    __shared__ float2 sOL[2*32];      // odd (layer1) record lane tables
    __shared__ float2 sOLoc[2*8];     // odd record local tables
    __shared__ float2 sEL[32], sFL[32];   // layer2 fused record lane tables
    __shared__ float2 sELoc[8], sFLoc[8]; // layer2 fused record local (x0.5 folded)
    __shared__ float2 sPair[21*4];
    __shared__ float2 sF01[8*4];      // Rx(x)·Ufinal(L0)
    __shared__ float2 sF12[8*4];      // Ry(x)·Ufinal(L1)
    __shared__ float2 sF2[8*4];       // Ufinal(L2)
    __shared__ float  sRed[8*8];
    __shared__ int    sLast;

    int tid  = threadIdx.x;
    int lane = tid & 31;
    int wid  = tid >> 5;
    int cta  = blockIdx.x;
    int b    = cta >> 3;
    int gw   = cta*WPC + wid;
    int br   = gw & 63;

    // ================= cooperative coefficient tables (189 jobs) ===========
    {
        int job = tid;
        if (job < 16){                       // layer-0 record per-qubit phases
            int r = job >> 3, q = job & 7;
            float s, c; __sincosf(0.5f*pw[r*8 + q], &s, &c);
            sT[r*8 + q] = make_float2(c, s);
        } else if (job < 24){                // data-rot (c,s)
            int q = job - 16;
            float s, c; __sincosf(0.5f*x[b*8 + q], &s, &c);
            sXcs[q] = make_float2(c, s);
        } else if (job < 88){                // odd record lane tables (r = 2,3)
            int k = job - 24; int r = k >> 5; int ln = k & 31;
            const float* pwa = pw + (2 + r)*8;
            float sum = 0.f;
            #pragma unroll
            for (int j = 0; j < 5; j++)
                if ((ln >> j) & 1) sum += pwa[3+j];
            float sp, cp; __sincosf(0.5f*sum, &sp, &cp);
            sOL[k] = make_float2(cp, sp);
        } else if (job < 104){               // odd record local tables
            int k = job - 88; int r = k >> 3; int i = k & 7;
            const float* pwa = pw + (2 + r)*8;
            float sum = 0.f;
            #pragma unroll
            for (int j = 0; j < 3; j++)
                if ((i >> j) & 1) sum += pwa[j];
            float sp, cp; __sincosf(0.5f*sum, &sp, &cp);
            sOLoc[k] = make_float2(cp, sp);
        } else if (job < 136){               // layer-2 fused record lane tables
            int ln = job - 104;
            const float* p4 = pw + 4*8;
            const float* p5 = pw + 5*8;
            float A = 0.f, B = 0.f;
            #pragma unroll
            for (int j = 0; j < 5; j++)
                if ((ln >> j) & 1){ A += p4[3+j]; B += p5[3+j]; }
            A *= 0.5f; B *= 0.5f;
            float sp, cp;
            __sincosf(A + B, &sp, &cp); sEL[ln] = make_float2(cp, sp);
            __sincosf(A - B, &sp, &cp); sFL[ln] = make_float2(cp, sp);
        } else if (job < 144){               // layer-2 fused record local tables
            int i = job - 136;
            const float* p4 = pw + 4*8;
            const float* p5 = pw + 5*8;
            float A = 0.f, B = 0.f;
            #pragma unroll
            for (int j = 0; j < 3; j++)
                if ((i >> j) & 1){ A += p4[j]; B += p5[j]; }
            A *= 0.5f; B *= 0.5f;
            float sp, cp;
            __sincosf(A + B, &sp, &cp); sELoc[i] = make_float2(0.5f*cp, 0.5f*sp);
            __sincosf(A - B, &sp, &cp); sFLoc[i] = make_float2(0.5f*cp, 0.5f*sp);
        } else if (job < 165){               // pair coefficients
            int k = job - 144; int layer = k/7, p = k - layer*7;
            const float* wl = w + layer*48 + 3*p;
            float ca, sa, cb, sb, cg, sg;
            __sincosf(0.5f*wl[0], &sa, &ca);
            __sincosf(0.5f*wl[1], &sb, &cb);
            __sincosf(0.5f*wl[2], &sg, &cg);
            float A  = ca*cb + sa*sb;
            float Bi = ca*sb - cb*sa;
            float C  = ca*cb - sa*sb;
            float Di = -(sa*cb + ca*sb);
            float2 pph = make_float2(cg, -sg);
            float2 qph = make_float2(cg,  sg);
            sPair[k*4+0] = make_float2(pph.x*A, pph.y*A);
            sPair[k*4+1] = cmul(pph, make_float2(0.f, Bi));
            sPair[k*4+2] = make_float2(qph.x*C, qph.y*C);
            sPair[k*4+3] = cmul(qph, make_float2(0.f, Di));
        } else if (job < 189){               // fused single-qubit matrices
            int k = job - 165;               // 0..23
            int grp = k >> 3, q = k & 7;
            float2 u00, u01, u10, u11;
            ufinal(w + grp*48 + 24 + 3*q, u00, u01, u10, u11);
            float2* dst;
            if (grp == 0){
                // Rx(x_q) * Ufinal0 :  Rx = [[c,-is],[-is,c]]
                float s, c; __sincosf(0.5f*x[b*8 + q], &s, &c);
                float2 ic = make_float2(c, 0.f), is = make_float2(0.f, -s);
                float2 n00 = cadd(cmul(ic,u00), cmul(is,u10));
                float2 n01 = cadd(cmul(ic,u01), cmul(is,u11));
                float2 n10 = cadd(cmul(is,u00), cmul(ic,u10));
                float2 n11 = cadd(cmul(is,u01), cmul(ic,u11));
                u00=n00; u01=n01; u10=n10; u11=n11;
                dst = sF01;
            } else if (grp == 1){
                // Ry(x_q) * Ufinal1 :  Ry = [[c,-s],[s,c]]
                float s, c; __sincosf(0.5f*x[b*8 + q], &s, &c);
                float2 n00 = make_float2(fmaf(c,u00.x,-s*u10.x), fmaf(c,u00.y,-s*u10.y));
                float2 n01 = make_float2(fmaf(c,u01.x,-s*u11.x), fmaf(c,u01.y,-s*u11.y));
                float2 n10 = make_float2(fmaf(s,u00.x, c*u10.x), fmaf(s,u00.y, c*u10.y));
                float2 n11 = make_float2(fmaf(s,u01.x, c*u11.x), fmaf(s,u01.y, c*u11.y));
                u00=n00; u01=n01; u10=n10; u11=n11;
                dst = sF12;
            } else dst = sF2;
            dst[q*4+0]=u00; dst[q*4+1]=u01; dst[q*4+2]=u10; dst[q*4+3]=u11;
        }
    }
    __syncthreads();

    // ================= product-state init (H + Ry(x) + layer-0 records) ====
    float2 a[8];
    {
        float sg0 = (br & 1) ? 1.f : -1.f;
        float sg1 = (br & 2) ? 1.f : -1.f;
        float2 g0[8], g1[8];
        #pragma unroll
        for (int q = 0; q < 8; q++){
            float2 t0 = sT[q], t1 = sT[8+q];
            float2 E = cmul(make_float2(t0.x, sg0*t0.y),
                            make_float2(t1.x, sg1*t1.y));
            float2 cs = sXcs[q];
            float gm = cs.x - cs.y, gp = cs.x + cs.y;
            g0[q] = make_float2(gm, 0.f);
            g1[q] = make_float2(gp*E.x, gp*E.y);
        }
        // lane product over qubits 3..7, scale K = (1/16)*RH^2 = 0.03125
        float2 lp = make_float2(0.03125f, 0.f);
        #pragma unroll
        for (int j = 0; j < 5; j++)
            lp = cmul(lp, ((lane >> j) & 1) ? g1[3+j] : g0[3+j]);
        float2 m00 = cmul(g0[0], g0[1]);
        float2 m10 = cmul(g1[0], g0[1]);
        float2 m01 = cmul(g0[0], g1[1]);
        float2 m11 = cmul(g1[0], g1[1]);
        #pragma unroll
        for (int i = 0; i < 8; i++){
            float2 mm = (i & 1) ? ((i & 2) ? m11 : m10) : ((i & 2) ? m01 : m00);
            a[i] = cmul(lp, cmul(mm, (i & 4) ? g1[2] : g0[2]));
        }
    }

    // ================= layer 0: pairs + CCRX ===============================
    {
        const float2* P = sPair;
        pair_LL(a, 0, 1, P[0], P[1], P[2], P[3]);
        if (br & 1){
            #pragma unroll
            for (int i = 0; i < 8; i++){
                if ((i & 1) && !(i & 2)){
                    int j = i | 2;
                    float2 ai = a[i], aj = a[j];
                    a[i] = make_float2(fmaf(c8, ai.x,  s8*aj.y), fmaf(c8, ai.y, -s8*aj.x));
                    a[j] = make_float2(fmaf(c8, aj.x,  s8*ai.y), fmaf(c8, aj.y, -s8*ai.x));
                }
            }
        }
        pair_ML(a, lane, 2, 0, P[4], P[5], P[6], P[7]);
        if (br & 2){
            #pragma unroll
            for (int i = 4; i < 8; i++){
                float2 p = shflx(a[i], 1);
                a[i] = make_float2(fmaf(c8, a[i].x,  s8*p.y), fmaf(c8, a[i].y, -s8*p.x));
            }
        }
        pair_NN(a, lane, 1, 2, P[8],  P[9],  P[10], P[11]);
        pair_NN(a, lane, 3, 4, P[12], P[13], P[14], P[15]);
        pair_LL(a, 1, 2,       P[16], P[17], P[18], P[19]);
        pair_NN(a, lane, 0, 1, P[20], P[21], P[22], P[23]);
        pair_NN(a, lane, 2, 3, P[24], P[25], P[26], P[27]);
    }

    // ================= layer 1 =============================================
    {
        // fused final(L0)*Rx(x)
        #pragma unroll
        for (int q = 0; q < 8; q++){
            float2 u00 = sF01[q*4+0], u01 = sF01[q*4+1];
            float2 u10 = sF01[q*4+2], u11 = sF01[q*4+3];
            if (q < 3) sq_local(a, q, u00, u01, u10, u11);
            else       sq_lane (a, lane, q-3, u00, u01, u10, u11);
        }
        // odd records (bits 2,3)
        #pragma unroll
        for (int i2 = 0; i2 < 2; i2++){
            int v = (br >> (2 + i2)) & 1;
            float2 eL = sOL[i2*32 + lane];
            #pragma unroll
            for (int i = 0; i < 8; i++){
                float2 e = cmul(eL, sOLoc[i2*8 + i]);
                if (v) a[i] = make_float2(a[i].y*e.y, -a[i].x*e.y);
                else   a[i] = make_float2(a[i].x*e.x,  a[i].y*e.x);
            }
        }
        const float2* P = sPair + 7*4;
        pair_LL(a, 0, 1, P[0], P[1], P[2], P[3]);
        if (br & 4){
            #pragma unroll
            for (int i = 0; i < 8; i++){
                if ((i & 1) && !(i & 2)){
                    int j = i | 2;
                    float2 ai = a[i], aj = a[j];
                    a[i] = make_float2(fmaf(c8, ai.x,  s8*aj.y), fmaf(c8, ai.y, -s8*aj.x));
                    a[j] = make_float2(fmaf(c8, aj.x,  s8*ai.y), fmaf(c8, aj.y, -s8*ai.x));
                }
            }
        }
        pair_ML(a, lane, 2, 0, P[4], P[5], P[6], P[7]);
        if (br & 8){
            #pragma unroll
            for (int i = 4; i < 8; i++){
                float2 p = shflx(a[i], 1);
                a[i] = make_float2(fmaf(c8, a[i].x,  s8*p.y), fmaf(c8, a[i].y, -s8*p.x));
            }
        }
        pair_NN(a, lane, 1, 2, P[8],  P[9],  P[10], P[11]);
        pair_NN(a, lane, 3, 4, P[12], P[13], P[14], P[15]);
        pair_LL(a, 1, 2,       P[16], P[17], P[18], P[19]);
        pair_NN(a, lane, 0, 1, P[20], P[21], P[22], P[23]);
        pair_NN(a, lane, 2, 3, P[24], P[25], P[26], P[27]);
    }

    // ================= layer 2 =============================================
    {
        // fused final(L1)*Ry(x)
        #pragma unroll
        for (int q = 0; q < 8; q++){
            float2 u00 = sF12[q*4+0], u01 = sF12[q*4+1];
            float2 u10 = sF12[q*4+2], u11 = sF12[q*4+3];
            if (q < 3) sq_local(a, q, u00, u01, u10, u11);
            else       sq_lane (a, lane, q-3, u00, u01, u10, u11);
        }
        // fused even records (bits 4,5): factor = (s4==s5 ? E : F), conj if !bit4
        {
            int v4 = (br >> 4) & 1, v5 = (br >> 5) & 1;
            bool same = (v4 == v5);
            float2 tL  = same ? sEL[lane] : sFL[lane];
            float cs = v4 ? 1.f : -1.f;
            #pragma unroll
            for (int i = 0; i < 8; i++){
                float2 tLoc = same ? sELoc[i] : sFLoc[i];
                float2 f = cmul(tL, tLoc);
                f.y *= cs;
                a[i] = cmul(a[i], f);
            }
        }
        const float2* P = sPair + 14*4;
        pair_LL(a, 0, 1, P[0], P[1], P[2], P[3]);
        if (br & 16){
            #pragma unroll
            for (int i = 0; i < 8; i++){
                if ((i & 1) && !(i & 2)){
                    int j = i | 2;
                    float2 ai = a[i], aj = a[j];
                    a[i] = make_float2(fmaf(c8, ai.x,  s8*aj.y), fmaf(c8, ai.y, -s8*aj.x));
                    a[j] = make_float2(fmaf(c8, aj.x,  s8*ai.y), fmaf(c8, aj.y, -s8*ai.x));
                }
            }
        }
        pair_ML(a, lane, 2, 0, P[4], P[5], P[6], P[7]);
        if (br & 32){
            #pragma unroll
            for (int i = 4; i < 8; i++){
                float2 p = shflx(a[i], 1);
                a[i] = make_float2(fmaf(c8, a[i].x,  s8*p.y), fmaf(c8, a[i].y, -s8*p.x));
            }
        }
        pair_NN(a, lane, 1, 2, P[8],  P[9],  P[10], P[11]);
        pair_NN(a, lane, 3, 4, P[12], P[13], P[14], P[15]);
        pair_LL(a, 1, 2,       P[16], P[17], P[18], P[19]);
        pair_NN(a, lane, 0, 1, P[20], P[21], P[22], P[23]);
        pair_NN(a, lane, 2, 3, P[24], P[25], P[26], P[27]);
        // final rotations of layer 2
        #pragma unroll
        for (int q = 0; q < 8; q++){
            float2 u00 = sF2[q*4+0], u01 = sF2[q*4+1];
            float2 u10 = sF2[q*4+2], u11 = sF2[q*4+3];
            if (q < 3) sq_local(a, q, u00, u01, u10, u11);
            else       sq_lane (a, lane, q-3, u00, u01, u10, u11);
        }
    }

    // ================= measurement & fused reduction =======================
    float e[8];
    float tot = 0.f;
    #pragma unroll
    for (int q = 0; q < 3; q++) e[q] = 0.f;
    #pragma unroll
    for (int i = 0; i < 8; i++){
        float p = fmaf(a[i].x, a[i].x, a[i].y*a[i].y);
        tot += p;
        #pragma unroll
        for (int q = 0; q < 3; q++)
            e[q] += ((i >> q) & 1) ? -p : p;
    }
    #pragma unroll
    for (int q = 0; q < 5; q++)
        e[3+q] = ((lane >> q) & 1) ? -tot : tot;

    #pragma unroll
    for (int q = 0; q < 8; q++){
        #pragma unroll
        for (int s = 16; s; s >>= 1)
            e[q] += __shfl_xor_sync(0xffffffffu, e[q], s);
    }
    if (lane == 0){
        #pragma unroll
        for (int q = 0; q < 8; q++) sRed[wid*8 + q] = e[q];
    }
    __syncthreads();

    if (tid < 8){
        float s = 0.f;
        #pragma unroll
        for (int wq = 0; wq < 8; wq++) s += sRed[wq*8 + tid];
        g_part[cta*8 + tid] = s;
        __threadfence();
    }
    __syncthreads();

    if (tid == 0){
        __threadfence();
        unsigned int t = atomicAdd(&g_ticket, 1u);
        sLast = (t == NCTA - 1) ? 1 : 0;
    }
    __syncthreads();

    if (sLast){
        __threadfence();
        if (tid < 128){
            int bb = tid >> 3, q = tid & 7;
            float s = 0.f;
            #pragma unroll
            for (int k = 0; k < 8; k++)
                s += g_part[(bb*8 + k)*8 + q];
            out[tid] = s;
        }
        __syncthreads();
        if (tid == 0) g_ticket = 0;
    }
}

extern "C" void kernel_launch(void* const* d_in, const int* in_sizes, int n_in,
                              void* d_out, int out_size){
    const float* x  = (const float*)d_in[0];   // (16, 8)
    const float* w  = (const float*)d_in[1];   // (3, 48)
    const float* pw = (const float*)d_in[2];   // (3, 2, 8)
    float* out = (float*)d_out;                // (16, 8)

    qpie_fused<<<NCTA, CTA_THREADS>>>(x, w, pw, out);
}